// round 3
// baseline (speedup 1.0000x reference)
#include <cuda_runtime.h>
#include <math.h>
#include <stdint.h>

#define Bsz 16384
#define Hd  1024
#define Cc  2
#define PPCc 24
#define Pp  48
#define EPSf 1e-4f

// Output layout (concatenated reference tuple, all fp32):
//   pos      [B,1]   at 0
//   shared   [B,H]   at B
//   logits   [B,C]   at B + B*H
//   distance [B,P]   at B + B*H + B*C
#define POS_OFF    ((size_t)0)
#define SHARED_OFF ((size_t)Bsz)
#define LOGITS_OFF (SHARED_OFF + (size_t)Bsz * Hd)
#define DIST_OFF   (LOGITS_OFF + (size_t)Bsz * Cc)

// Scratch (no device allocs allowed)
__device__ float g_p2[Pp];
__device__ float g_simSum[Pp];
__device__ float g_uall[Pp * Hd];        // u_p = W^T proto_p, all 48
__device__ float g_posall[(size_t)Bsz * Pp];  // shared @ U^T  (3 MB)

__device__ __forceinline__ uint32_t f2tf(float f) {
    uint32_t r;
    asm("cvt.rna.tf32.f32 %0, %1;" : "=r"(r) : "f"(f));
    return r;
}

// ---------------------------------------------------------------------------
// K0: block 0 zeroes g_uall + g_simSum; blocks 1..48 compute ||proto_p||^2
// ---------------------------------------------------------------------------
__global__ void k0_init(const float* __restrict__ protos) {
    const int b   = blockIdx.x;
    const int tid = threadIdx.x;
    if (b == 0) {
        if (tid < Pp) g_simSum[tid] = 0.f;
        float4* z = (float4*)g_uall;
        for (int i = tid; i < Pp * Hd / 4; i += 256)
            z[i] = make_float4(0.f, 0.f, 0.f, 0.f);
        return;
    }
    const int p = b - 1;
    const float* pr = protos + (size_t)p * Hd;
    float s = 0.f;
    for (int t = tid; t < Hd; t += 256) { float v = pr[t]; s = fmaf(v, v, s); }
    __shared__ float red[8];
    for (int o = 16; o; o >>= 1) s += __shfl_xor_sync(0xffffffffu, s, o);
    const int lane = tid & 31, w = tid >> 5;
    if (lane == 0) red[w] = s;
    __syncthreads();
    if (w == 0) {
        s = (lane < 8) ? red[lane] : 0.f;
        for (int o = 4; o; o >>= 1) s += __shfl_xor_sync(0xffffffffu, s, o);
        if (lane == 0) g_p2[p] = s;
    }
}

// ---------------------------------------------------------------------------
// K1: u_all[p][j] = sum_i protos[p][i] * W[i][j]   (split-K atomics, depth 8)
// grid 32: block b -> j0 = (b&3)*256, i0 = (b>>2)*128
// ---------------------------------------------------------------------------
__global__ __launch_bounds__(256) void k1_uall(
    const float* __restrict__ protos, const float* __restrict__ W) {
    __shared__ float psh[Pp * 128];
    const int b = blockIdx.x, t = threadIdx.x;
    const int j0 = (b & 3) * 256;
    const int i0 = (b >> 2) * 128;
    for (int idx = t; idx < Pp * 128; idx += 256) {
        const int p = idx >> 7, i = idx & 127;
        psh[idx] = protos[(size_t)p * Hd + i0 + i];
    }
    __syncthreads();
    const int j = j0 + t;
    float acc[Pp];
#pragma unroll
    for (int p = 0; p < Pp; p++) acc[p] = 0.f;
    const float* Wp = W + (size_t)i0 * Hd + j;
    for (int i = 0; i < 128; i += 4) {
        const float w0 = Wp[(size_t)(i + 0) * Hd];
        const float w1 = Wp[(size_t)(i + 1) * Hd];
        const float w2 = Wp[(size_t)(i + 2) * Hd];
        const float w3 = Wp[(size_t)(i + 3) * Hd];
#pragma unroll
        for (int p = 0; p < Pp; p++) {
            const float4 pv = *(const float4*)&psh[p * 128 + i];
            float a = acc[p];
            a = fmaf(w0, pv.x, a); a = fmaf(w1, pv.y, a);
            a = fmaf(w2, pv.z, a); a = fmaf(w3, pv.w, a);
            acc[p] = a;
        }
    }
#pragma unroll
    for (int p = 0; p < Pp; p++)
        atomicAdd(&g_uall[p * Hd + j], acc[p]);
}

// ---------------------------------------------------------------------------
// K2 mega: two tf32 mma GEMMs in one launch.
//   role 0 (even blocks): distance/similarity/logits/simSum over x vs protos
//   role 1 (odd blocks):  pos_all = shared @ U^T, fused shared copy-out
// Block tile 64 rows x 48 cols; 8 warps: warp w -> rows (w&3)*16.., n-half w>>2.
// ---------------------------------------------------------------------------
__global__ __launch_bounds__(256) void k2_mega(
    const float* __restrict__ x, const float* __restrict__ shr,
    const float* __restrict__ protos, const float* __restrict__ llw,
    float* __restrict__ out) {
    __shared__ uint32_t xs[64 * 36];
    __shared__ uint32_t ps[48 * 36];
    __shared__ float x2s[64];
    __shared__ float p2s[48];
    __shared__ float wks[96];
    __shared__ float logit_s[128];
    __shared__ float simPart[48];

    const int tid  = threadIdx.x;
    const int lane = tid & 31, warp = tid >> 5;
    const int role = blockIdx.x & 1;
    const int row0 = (blockIdx.x >> 1) * 64;
    const int g  = lane >> 2;
    const int t4 = lane & 3;

    if (!role) {
        if (tid < 64)  x2s[tid] = 0.f;
        if (tid < 48)  { p2s[tid] = g_p2[tid]; simPart[tid] = 0.f; }
        if (tid < 96)  wks[tid] = llw[tid];
        if (tid < 128) logit_s[tid] = 0.f;
    }

    const float* A  = role ? shr : x;
    const float* Bm = role ? (const float*)g_uall : protos;

    const int xrow = tid >> 3;            // 0..31 (second row +32)
    const int xk4  = (tid & 7) << 2;
    const float* xbase = A + (size_t)(row0 + xrow) * Hd + xk4;
    const float* pbase0 = Bm + (size_t)xrow * Hd + xk4;
    const float* pbase1 = Bm + (size_t)(xrow + 32) * Hd + xk4;
    const bool   phas1  = (tid < 128);

    float4 xc0 = *(const float4*)(xbase);
    float4 xc1 = *(const float4*)(xbase + (size_t)32 * Hd);
    float4 pc0 = *(const float4*)pbase0;
    float4 pc1 = phas1 ? *(const float4*)pbase1 : make_float4(0.f, 0.f, 0.f, 0.f);

    float acc[3][4];
#pragma unroll
    for (int n = 0; n < 3; n++)
#pragma unroll
        for (int q = 0; q < 4; q++) acc[n][q] = 0.f;
    float sq0 = 0.f, sq1 = 0.f;

    const int Rg    = (warp & 3) * 16 + g;
    const int nhalf = warp >> 2;

    float* cpy = out + SHARED_OFF + (size_t)(row0 + xrow) * Hd + xk4;

    for (int s = 0; s < 32; s++) {
        if (s) __syncthreads();

        float4 xn0, xn1, pn0, pn1;
        if (s < 31) {
            const int ko = (s + 1) * 32;
            xn0 = *(const float4*)(xbase + ko);
            xn1 = *(const float4*)(xbase + (size_t)32 * Hd + ko);
            pn0 = *(const float4*)(pbase0 + ko);
            if (phas1) pn1 = *(const float4*)(pbase1 + ko);
        }

        if (!role) {
            sq0 = fmaf(xc0.x, xc0.x, sq0); sq0 = fmaf(xc0.y, xc0.y, sq0);
            sq0 = fmaf(xc0.z, xc0.z, sq0); sq0 = fmaf(xc0.w, xc0.w, sq0);
            sq1 = fmaf(xc1.x, xc1.x, sq1); sq1 = fmaf(xc1.y, xc1.y, sq1);
            sq1 = fmaf(xc1.z, xc1.z, sq1); sq1 = fmaf(xc1.w, xc1.w, sq1);
        } else {
            // fused shared_user copy-out (exactly once per element)
            *(float4*)(cpy + s * 32)                    = xc0;
            *(float4*)(cpy + (size_t)32 * Hd + s * 32)  = xc1;
        }

        // tf32 convert + 16B shared stores
        {
            uint4 v;
            v.x = f2tf(xc0.x); v.y = f2tf(xc0.y); v.z = f2tf(xc0.z); v.w = f2tf(xc0.w);
            *(uint4*)&xs[xrow * 36 + xk4] = v;
            v.x = f2tf(xc1.x); v.y = f2tf(xc1.y); v.z = f2tf(xc1.z); v.w = f2tf(xc1.w);
            *(uint4*)&xs[(xrow + 32) * 36 + xk4] = v;
            v.x = f2tf(pc0.x); v.y = f2tf(pc0.y); v.z = f2tf(pc0.z); v.w = f2tf(pc0.w);
            *(uint4*)&ps[xrow * 36 + xk4] = v;
            if (phas1) {
                v.x = f2tf(pc1.x); v.y = f2tf(pc1.y); v.z = f2tf(pc1.z); v.w = f2tf(pc1.w);
                *(uint4*)&ps[(xrow + 32) * 36 + xk4] = v;
            }
        }
        __syncthreads();

#pragma unroll
        for (int kc = 0; kc < 32; kc += 8) {
            const uint32_t a0 = xs[(Rg    ) * 36 + kc + t4];
            const uint32_t a1 = xs[(Rg + 8) * 36 + kc + t4];
            const uint32_t a2 = xs[(Rg    ) * 36 + kc + t4 + 4];
            const uint32_t a3 = xs[(Rg + 8) * 36 + kc + t4 + 4];
#pragma unroll
            for (int nt = 0; nt < 3; nt++) {
                const int prow = (nhalf * 3 + nt) * 8 + g;
                const uint32_t b0 = ps[prow * 36 + kc + t4];
                const uint32_t b1 = ps[prow * 36 + kc + t4 + 4];
                asm volatile(
                    "mma.sync.aligned.m16n8k8.row.col.f32.tf32.tf32.f32 "
                    "{%0,%1,%2,%3}, {%4,%5,%6,%7}, {%8,%9}, {%0,%1,%2,%3};"
                    : "+f"(acc[nt][0]), "+f"(acc[nt][1]),
                      "+f"(acc[nt][2]), "+f"(acc[nt][3])
                    : "r"(a0), "r"(a1), "r"(a2), "r"(a3), "r"(b0), "r"(b1));
            }
        }

        if (s < 31) {
            xc0 = xn0; xc1 = xn1;
            pc0 = pn0; if (phas1) pc1 = pn1;
        }
    }

    const int ra = Rg, rb = Rg + 8;

    if (role) {
        // pos_all epilogue: plain dot products
        float* pa = g_posall + (size_t)row0 * 48;
#pragma unroll
        for (int nt = 0; nt < 3; nt++) {
            const int c0 = (nhalf * 3 + nt) * 8 + t4 * 2;
            *(float2*)(pa + (size_t)ra * 48 + c0) = make_float2(acc[nt][0], acc[nt][1]);
            *(float2*)(pa + (size_t)rb * 48 + c0) = make_float2(acc[nt][2], acc[nt][3]);
        }
        return;
    }

    __syncthreads();
    atomicAdd(&x2s[xrow],      sq0);
    atomicAdd(&x2s[xrow + 32], sq1);
    __syncthreads();

    const float x2a = x2s[ra], x2b = x2s[rb];
    float lgA0 = 0.f, lgA1 = 0.f, lgB0 = 0.f, lgB1 = 0.f;
    float* dd = out + DIST_OFF + (size_t)row0 * 48;
#pragma unroll
    for (int nt = 0; nt < 3; nt++) {
        const int c0 = (nhalf * 3 + nt) * 8 + t4 * 2, c1 = c0 + 1;
        const float dA0 = fmaf(-2.f, acc[nt][0], x2a + p2s[c0]);
        const float dA1 = fmaf(-2.f, acc[nt][1], x2a + p2s[c1]);
        const float dB0 = fmaf(-2.f, acc[nt][2], x2b + p2s[c0]);
        const float dB1 = fmaf(-2.f, acc[nt][3], x2b + p2s[c1]);
        *(float2*)(dd + (size_t)ra * 48 + c0) = make_float2(dA0, dA1);
        *(float2*)(dd + (size_t)rb * 48 + c0) = make_float2(dB0, dB1);
        const float sA0 = logf((dA0 + 1.f) / (dA0 + EPSf));
        const float sA1 = logf((dA1 + 1.f) / (dA1 + EPSf));
        const float sB0 = logf((dB0 + 1.f) / (dB0 + EPSf));
        const float sB1 = logf((dB1 + 1.f) / (dB1 + EPSf));
        lgA0 = fmaf(sA0, wks[c0], lgA0); lgA0 = fmaf(sA1, wks[c1], lgA0);
        lgA1 = fmaf(sA0, wks[48 + c0], lgA1); lgA1 = fmaf(sA1, wks[48 + c1], lgA1);
        lgB0 = fmaf(sB0, wks[c0], lgB0); lgB0 = fmaf(sB1, wks[c1], lgB0);
        lgB1 = fmaf(sB0, wks[48 + c0], lgB1); lgB1 = fmaf(sB1, wks[48 + c1], lgB1);
        atomicAdd(&simPart[c0], sA0 + sB0);
        atomicAdd(&simPart[c1], sA1 + sB1);
    }
    atomicAdd(&logit_s[ra * 2 + 0], lgA0);
    atomicAdd(&logit_s[ra * 2 + 1], lgA1);
    atomicAdd(&logit_s[rb * 2 + 0], lgB0);
    atomicAdd(&logit_s[rb * 2 + 1], lgB1);
    __syncthreads();

    if (tid < 128) out[LOGITS_OFF + (size_t)row0 * 2 + tid] = logit_s[tid];
    if (tid < 48)  atomicAdd(&g_simSum[tid], simPart[tid]);
}

// ---------------------------------------------------------------------------
// K3: per-block redundant argmax over class columns, then gather pos column
// ---------------------------------------------------------------------------
__global__ __launch_bounds__(256) void k3_final(
    const float* __restrict__ bb, const int* __restrict__ flag,
    float* __restrict__ out) {
    __shared__ int js;
    const int tid = threadIdx.x;
    if (tid < 32) {
        const int idx = (flag[0] != 0) ? 1 : 0;
        float v = (tid < PPCc) ? g_simSum[idx * PPCc + tid] : -INFINITY;
        int bj = tid;
        for (int o = 16; o; o >>= 1) {
            const float ov = __shfl_xor_sync(0xffffffffu, v, o);
            const int   oj = __shfl_xor_sync(0xffffffffu, bj, o);
            if (ov > v || (ov == v && oj < bj)) { v = ov; bj = oj; }
        }
        if (tid == 0) js = idx * PPCc + bj;
    }
    __syncthreads();
    const int r = blockIdx.x * 256 + tid;
    out[POS_OFF + r] = g_posall[(size_t)r * 48 + js] + bb[0];
}

// ---------------------------------------------------------------------------
extern "C" void kernel_launch(void* const* d_in, const int* in_sizes, int n_in,
                              void* d_out, int out_size) {
    const float* x      = (const float*)d_in[0];  // specific_user [B,H]
    const float* shr    = (const float*)d_in[1];  // shared_user   [B,H]
    const float* protos = (const float*)d_in[2];  // [P,H]
    const float* llw    = (const float*)d_in[3];  // [C,P]
    const float* W      = (const float*)d_in[4];  // [1,H,H]
    const float* bb     = (const float*)d_in[5];  // [1]
    const int*   flag   = (const int*)d_in[6];    // scalar
    float* out = (float*)d_out;

    k0_init <<<Pp + 1, 256>>>(protos);
    k1_uall <<<32, 256>>>(protos, W);
    k2_mega <<<(Bsz / 64) * 2, 256>>>(x, shr, protos, llw, out);
    k3_final<<<Bsz / 256, 256>>>(bb, flag, out);
}

// round 4
// speedup vs baseline: 1.4833x; 1.4833x over previous
#include <cuda_runtime.h>
#include <math.h>
#include <stdint.h>

#define Bsz 16384
#define Hd  1024
#define Cc  2
#define PPCc 24
#define Pp  48
#define EPSf 1e-4f

// Output layout (concatenated reference tuple, all fp32):
//   pos      [B,1]   at 0
//   shared   [B,H]   at B
//   logits   [B,C]   at B + B*H
//   distance [B,P]   at B + B*H + B*C
#define POS_OFF    ((size_t)0)
#define SHARED_OFF ((size_t)Bsz)
#define LOGITS_OFF (SHARED_OFF + (size_t)Bsz * Hd)
#define DIST_OFF   (LOGITS_OFF + (size_t)Bsz * Cc)

// Scratch (no device allocs allowed)
__device__ float g_p2[Pp];
__device__ float g_simSum[Pp];
__device__ float g_uall[Pp * Hd];   // u_p = W^T proto_p, all 48 (exact fp32)

__device__ __forceinline__ uint32_t f2tf(float f) {
    uint32_t r;
    asm("cvt.rna.tf32.f32 %0, %1;" : "=r"(r) : "f"(f));
    return r;
}

// ---------------------------------------------------------------------------
// K0: block 0 zeroes g_uall + g_simSum; blocks 1..48 compute ||proto_p||^2
// ---------------------------------------------------------------------------
__global__ void k0_prep(const float* __restrict__ protos) {
    const int b   = blockIdx.x;
    const int tid = threadIdx.x;
    if (b == 0) {
        if (tid < Pp) g_simSum[tid] = 0.f;
        float4* z = (float4*)g_uall;
        for (int i = tid; i < Pp * Hd / 4; i += 256)
            z[i] = make_float4(0.f, 0.f, 0.f, 0.f);
        return;
    }
    const int p = b - 1;
    const float* pr = protos + (size_t)p * Hd;
    float s = 0.f;
    for (int t = tid; t < Hd; t += 256) { float v = pr[t]; s = fmaf(v, v, s); }
    __shared__ float red[8];
    for (int o = 16; o; o >>= 1) s += __shfl_xor_sync(0xffffffffu, s, o);
    const int lane = tid & 31, w = tid >> 5;
    if (lane == 0) red[w] = s;
    __syncthreads();
    if (w == 0) {
        s = (lane < 8) ? red[lane] : 0.f;
        for (int o = 4; o; o >>= 1) s += __shfl_xor_sync(0xffffffffu, s, o);
        if (lane == 0) g_p2[p] = s;
    }
}

// ---------------------------------------------------------------------------
// K1: u_all[p][j] = sum_i protos[p][i] * W[i][j]   (split-K atomics)
// grid 64: block b -> j0 = (b&3)*256, i0 = (b>>2)*64 (16-way split over i)
// Exact fp32; independent of the distance pipeline.
// ---------------------------------------------------------------------------
__global__ __launch_bounds__(256) void k1_uall(
    const float* __restrict__ protos, const float* __restrict__ W) {
    __shared__ float psh[Pp * 64];
    const int b = blockIdx.x, t = threadIdx.x;
    const int j0 = (b & 3) * 256;
    const int i0 = (b >> 2) * 64;
    for (int idx = t; idx < Pp * 64; idx += 256) {
        const int p = idx >> 6, i = idx & 63;
        psh[idx] = protos[(size_t)p * Hd + i0 + i];
    }
    __syncthreads();
    const int j = j0 + t;
    float acc[Pp];
#pragma unroll
    for (int p = 0; p < Pp; p++) acc[p] = 0.f;
    const float* Wp = W + (size_t)i0 * Hd + j;
    for (int i = 0; i < 64; i += 4) {
        const float w0 = __ldcs(Wp + (size_t)(i + 0) * Hd);
        const float w1 = __ldcs(Wp + (size_t)(i + 1) * Hd);
        const float w2 = __ldcs(Wp + (size_t)(i + 2) * Hd);
        const float w3 = __ldcs(Wp + (size_t)(i + 3) * Hd);
#pragma unroll
        for (int p = 0; p < Pp; p++) {
            const float4 pv = *(const float4*)&psh[p * 64 + i];
            float a = acc[p];
            a = fmaf(w0, pv.x, a); a = fmaf(w1, pv.y, a);
            a = fmaf(w2, pv.z, a); a = fmaf(w3, pv.w, a);
            acc[p] = a;
        }
    }
#pragma unroll
    for (int p = 0; p < Pp; p++)
        atomicAdd(&g_uall[p * Hd + j], acc[p]);
}

// ---------------------------------------------------------------------------
// K2: distance GEMM via tf32 mma.sync (m16n8k8).
// 256 blocks x 64 rows (fills all 148 SMs, ~1.7 blocks/SM for latency hiding).
// 8 warps: warp w -> rows (w&3)*16..+16, col half w>>2 (24 cols each).
// Register double-buffered gmem->smem staging; x^2 folded into the loader.
// Epilogue: distance (__stcs), log-similarity, logits, per-proto sim sums.
// ---------------------------------------------------------------------------
__global__ __launch_bounds__(256) void k2_dist(
    const float* __restrict__ x, const float* __restrict__ protos,
    const float* __restrict__ llw, float* __restrict__ out) {
    __shared__ uint32_t xs[64 * 36];
    __shared__ uint32_t ps[48 * 36];
    __shared__ float x2s[64];
    __shared__ float p2s[48];
    __shared__ float wks[96];
    __shared__ float logit_s[128];
    __shared__ float simPart[48];

    const int tid  = threadIdx.x;
    const int lane = tid & 31, warp = tid >> 5;
    const int row0 = blockIdx.x * 64;
    const int g  = lane >> 2;
    const int t4 = lane & 3;

    if (tid < 64)  x2s[tid] = 0.f;
    if (tid < 48)  { p2s[tid] = g_p2[tid]; simPart[tid] = 0.f; }
    if (tid < 96)  wks[tid] = llw[tid];
    if (tid < 128) logit_s[tid] = 0.f;

    const int xrow = tid >> 3;            // 0..31 (second row +32)
    const int xk4  = (tid & 7) << 2;
    const float* xbase  = x + (size_t)(row0 + xrow) * Hd + xk4;
    const float* pbase0 = protos + (size_t)xrow * Hd + xk4;
    const float* pbase1 = protos + (size_t)(xrow + 32) * Hd + xk4;
    const bool   phas1  = (tid < 128);    // proto rows 32..47

    float4 xc0 = *(const float4*)(xbase);
    float4 xc1 = *(const float4*)(xbase + (size_t)32 * Hd);
    float4 pc0 = *(const float4*)pbase0;
    float4 pc1 = phas1 ? *(const float4*)pbase1 : make_float4(0.f, 0.f, 0.f, 0.f);

    float acc[3][4];
#pragma unroll
    for (int n = 0; n < 3; n++)
#pragma unroll
        for (int q = 0; q < 4; q++) acc[n][q] = 0.f;
    float sq0 = 0.f, sq1 = 0.f;

    const int Rg    = (warp & 3) * 16 + g;
    const int nhalf = warp >> 2;

    for (int s = 0; s < 32; s++) {
        if (s) __syncthreads();

        float4 xn0, xn1, pn0, pn1;
        if (s < 31) {
            const int ko = (s + 1) * 32;
            xn0 = __ldcs((const float4*)(xbase + ko));
            xn1 = __ldcs((const float4*)(xbase + (size_t)32 * Hd + ko));
            pn0 = __ldg((const float4*)(pbase0 + ko));
            if (phas1) pn1 = __ldg((const float4*)(pbase1 + ko));
        }

        sq0 = fmaf(xc0.x, xc0.x, sq0); sq0 = fmaf(xc0.y, xc0.y, sq0);
        sq0 = fmaf(xc0.z, xc0.z, sq0); sq0 = fmaf(xc0.w, xc0.w, sq0);
        sq1 = fmaf(xc1.x, xc1.x, sq1); sq1 = fmaf(xc1.y, xc1.y, sq1);
        sq1 = fmaf(xc1.z, xc1.z, sq1); sq1 = fmaf(xc1.w, xc1.w, sq1);

        {
            uint4 v;
            v.x = f2tf(xc0.x); v.y = f2tf(xc0.y); v.z = f2tf(xc0.z); v.w = f2tf(xc0.w);
            *(uint4*)&xs[xrow * 36 + xk4] = v;
            v.x = f2tf(xc1.x); v.y = f2tf(xc1.y); v.z = f2tf(xc1.z); v.w = f2tf(xc1.w);
            *(uint4*)&xs[(xrow + 32) * 36 + xk4] = v;
            v.x = f2tf(pc0.x); v.y = f2tf(pc0.y); v.z = f2tf(pc0.z); v.w = f2tf(pc0.w);
            *(uint4*)&ps[xrow * 36 + xk4] = v;
            if (phas1) {
                v.x = f2tf(pc1.x); v.y = f2tf(pc1.y); v.z = f2tf(pc1.z); v.w = f2tf(pc1.w);
                *(uint4*)&ps[(xrow + 32) * 36 + xk4] = v;
            }
        }
        __syncthreads();

#pragma unroll
        for (int kc = 0; kc < 32; kc += 8) {
            const uint32_t a0 = xs[(Rg    ) * 36 + kc + t4];
            const uint32_t a1 = xs[(Rg + 8) * 36 + kc + t4];
            const uint32_t a2 = xs[(Rg    ) * 36 + kc + t4 + 4];
            const uint32_t a3 = xs[(Rg + 8) * 36 + kc + t4 + 4];
#pragma unroll
            for (int nt = 0; nt < 3; nt++) {
                const int prow = (nhalf * 3 + nt) * 8 + g;
                const uint32_t b0 = ps[prow * 36 + kc + t4];
                const uint32_t b1 = ps[prow * 36 + kc + t4 + 4];
                asm volatile(
                    "mma.sync.aligned.m16n8k8.row.col.f32.tf32.tf32.f32 "
                    "{%0,%1,%2,%3}, {%4,%5,%6,%7}, {%8,%9}, {%0,%1,%2,%3};"
                    : "+f"(acc[nt][0]), "+f"(acc[nt][1]),
                      "+f"(acc[nt][2]), "+f"(acc[nt][3])
                    : "r"(a0), "r"(a1), "r"(a2), "r"(a3), "r"(b0), "r"(b1));
            }
        }

        if (s < 31) {
            xc0 = xn0; xc1 = xn1;
            pc0 = pn0; if (phas1) pc1 = pn1;
        }
    }

    __syncthreads();
    atomicAdd(&x2s[xrow],      sq0);
    atomicAdd(&x2s[xrow + 32], sq1);
    __syncthreads();

    const int ra = Rg, rb = Rg + 8;
    const float x2a = x2s[ra], x2b = x2s[rb];
    float lgA0 = 0.f, lgA1 = 0.f, lgB0 = 0.f, lgB1 = 0.f;
    float* dd = out + DIST_OFF + (size_t)row0 * 48;
#pragma unroll
    for (int nt = 0; nt < 3; nt++) {
        const int c0 = (nhalf * 3 + nt) * 8 + t4 * 2, c1 = c0 + 1;
        const float dA0 = fmaf(-2.f, acc[nt][0], x2a + p2s[c0]);
        const float dA1 = fmaf(-2.f, acc[nt][1], x2a + p2s[c1]);
        const float dB0 = fmaf(-2.f, acc[nt][2], x2b + p2s[c0]);
        const float dB1 = fmaf(-2.f, acc[nt][3], x2b + p2s[c1]);
        __stcs((float2*)(dd + (size_t)ra * 48 + c0), make_float2(dA0, dA1));
        __stcs((float2*)(dd + (size_t)rb * 48 + c0), make_float2(dB0, dB1));
        const float sA0 = logf((dA0 + 1.f) / (dA0 + EPSf));
        const float sA1 = logf((dA1 + 1.f) / (dA1 + EPSf));
        const float sB0 = logf((dB0 + 1.f) / (dB0 + EPSf));
        const float sB1 = logf((dB1 + 1.f) / (dB1 + EPSf));
        lgA0 = fmaf(sA0, wks[c0], lgA0); lgA0 = fmaf(sA1, wks[c1], lgA0);
        lgA1 = fmaf(sA0, wks[48 + c0], lgA1); lgA1 = fmaf(sA1, wks[48 + c1], lgA1);
        lgB0 = fmaf(sB0, wks[c0], lgB0); lgB0 = fmaf(sB1, wks[c1], lgB0);
        lgB1 = fmaf(sB0, wks[48 + c0], lgB1); lgB1 = fmaf(sB1, wks[48 + c1], lgB1);
        atomicAdd(&simPart[c0], sA0 + sB0);
        atomicAdd(&simPart[c1], sA1 + sB1);
    }
    atomicAdd(&logit_s[ra * 2 + 0], lgA0);
    atomicAdd(&logit_s[ra * 2 + 1], lgA1);
    atomicAdd(&logit_s[rb * 2 + 0], lgB0);
    atomicAdd(&logit_s[rb * 2 + 1], lgB1);
    __syncthreads();

    if (tid < 128) out[LOGITS_OFF + (size_t)row0 * 2 + tid] = logit_s[tid];
    if (tid < 48)  atomicAdd(&g_simSum[tid], simPart[tid]);
}

// ---------------------------------------------------------------------------
// K3: in-block argmax -> u[jstar] to smem -> fused shared copy-out + pos dot.
// 512 threads, 16 rows per block (one warp per row), exact fp32.
// ---------------------------------------------------------------------------
__global__ __launch_bounds__(512) void k3_pos(
    const float* __restrict__ shr, const float* __restrict__ bb,
    const int* __restrict__ flag, float* __restrict__ out) {
    __shared__ float us[Hd];
    __shared__ int   js_s;
    const int tid = threadIdx.x;

    if (tid < 32) {
        const int idx = (flag[0] != 0) ? 1 : 0;
        float v = (tid < PPCc) ? g_simSum[idx * PPCc + tid] : -INFINITY;
        int bj = tid;
        for (int o = 16; o; o >>= 1) {
            const float ov = __shfl_xor_sync(0xffffffffu, v, o);
            const int   oj = __shfl_xor_sync(0xffffffffu, bj, o);
            if (ov > v || (ov == v && oj < bj)) { v = ov; bj = oj; }
        }
        if (tid == 0) js_s = idx * PPCc + bj;
    }
    __syncthreads();
    const int js = js_s;
    for (int i = tid; i < Hd; i += 512) us[i] = g_uall[js * Hd + i];
    __syncthreads();

    const int warp = tid >> 5, lane = tid & 31;
    const int r = blockIdx.x * 16 + warp;
    const float4* src = (const float4*)(shr + (size_t)r * Hd);
    float4*       dst = (float4*)(out + SHARED_OFF + (size_t)r * Hd);
    const float4* uf  = (const float4*)us;
    float acc = 0.f;
#pragma unroll
    for (int t = lane; t < Hd / 4; t += 32) {
        const float4 v = __ldcs(src + t);
        __stcs(dst + t, v);
        const float4 u4 = uf[t];
        acc = fmaf(v.x, u4.x, acc);
        acc = fmaf(v.y, u4.y, acc);
        acc = fmaf(v.z, u4.z, acc);
        acc = fmaf(v.w, u4.w, acc);
    }
    for (int o = 16; o; o >>= 1) acc += __shfl_xor_sync(0xffffffffu, acc, o);
    if (lane == 0) out[POS_OFF + r] = acc + __ldg(bb);
}

// ---------------------------------------------------------------------------
extern "C" void kernel_launch(void* const* d_in, const int* in_sizes, int n_in,
                              void* d_out, int out_size) {
    const float* x      = (const float*)d_in[0];  // specific_user [B,H]
    const float* shr    = (const float*)d_in[1];  // shared_user   [B,H]
    const float* protos = (const float*)d_in[2];  // [P,H]
    const float* llw    = (const float*)d_in[3];  // [C,P]
    const float* W      = (const float*)d_in[4];  // [1,H,H]
    const float* bb     = (const float*)d_in[5];  // [1]
    const int*   flag   = (const int*)d_in[6];    // scalar
    float* out = (float*)d_out;

    k0_prep<<<Pp + 1, 256>>>(protos);
    k1_uall<<<64, 256>>>(protos, W);
    k2_dist<<<Bsz / 64, 256>>>(x, protos, llw, out);
    k3_pos <<<Bsz / 16, 512>>>(shr, bb, flag, out);
}

// round 5
// speedup vs baseline: 1.5920x; 1.0732x over previous
#include <cuda_runtime.h>
#include <math.h>
#include <stdint.h>

#define Bsz 16384
#define Hd  1024
#define Cc  2
#define PPCc 24
#define Pp  48
#define EPSf 1e-4f

// Output layout (concatenated reference tuple, all fp32):
//   pos      [B,1]   at 0
//   shared   [B,H]   at B
//   logits   [B,C]   at B + B*H
//   distance [B,P]   at B + B*H + B*C
#define POS_OFF    ((size_t)0)
#define SHARED_OFF ((size_t)Bsz)
#define LOGITS_OFF (SHARED_OFF + (size_t)Bsz * Hd)
#define DIST_OFF   (LOGITS_OFF + (size_t)Bsz * Cc)

// Scratch (no device allocs allowed; zeroed via cudaMemsetAsync graph nodes)
__device__ float g_simSum[Pp];
__device__ float g_uall[Pp * Hd];   // u_p = W^T proto_p, all 48 (exact fp32)

__device__ __forceinline__ uint32_t f2tf(float f) {
    uint32_t r;
    asm("cvt.rna.tf32.f32 %0, %1;" : "=r"(r) : "f"(f));
    return r;
}

// ---------------------------------------------------------------------------
// K1: u_all[p][j] = sum_i protos[p][i] * W[i][j]   (split-K atomics)
// grid 64: block b -> j0 = (b&3)*256, i0 = (b>>2)*64 (16-way split over i)
// Exact fp32; independent of the distance pipeline.
// ---------------------------------------------------------------------------
__global__ __launch_bounds__(256) void k1_uall(
    const float* __restrict__ protos, const float* __restrict__ W) {
    __shared__ float psh[Pp * 64];
    const int b = blockIdx.x, t = threadIdx.x;
    const int j0 = (b & 3) * 256;
    const int i0 = (b >> 2) * 64;
    for (int idx = t; idx < Pp * 64; idx += 256) {
        const int p = idx >> 6, i = idx & 63;
        psh[idx] = protos[(size_t)p * Hd + i0 + i];
    }
    __syncthreads();
    const int j = j0 + t;
    float acc[Pp];
#pragma unroll
    for (int p = 0; p < Pp; p++) acc[p] = 0.f;
    const float* Wp = W + (size_t)i0 * Hd + j;
    for (int i = 0; i < 64; i += 4) {
        const float w0 = __ldcs(Wp + (size_t)(i + 0) * Hd);
        const float w1 = __ldcs(Wp + (size_t)(i + 1) * Hd);
        const float w2 = __ldcs(Wp + (size_t)(i + 2) * Hd);
        const float w3 = __ldcs(Wp + (size_t)(i + 3) * Hd);
#pragma unroll
        for (int p = 0; p < Pp; p++) {
            const float4 pv = *(const float4*)&psh[p * 64 + i];
            float a = acc[p];
            a = fmaf(w0, pv.x, a); a = fmaf(w1, pv.y, a);
            a = fmaf(w2, pv.z, a); a = fmaf(w3, pv.w, a);
            acc[p] = a;
        }
    }
#pragma unroll
    for (int p = 0; p < Pp; p++)
        atomicAdd(&g_uall[p * Hd + j], acc[p]);
}

// ---------------------------------------------------------------------------
// K2: distance GEMM via tf32 mma.sync (m16n8k8), double-buffered smem,
// ONE __syncthreads per K-stage. 256 blocks x 64 rows.
// Iteration s: store regs(tile s)->buf[s&1]; bar; LDG tile s+1; mma buf[s&1].
// x^2 AND p^2 folded into the staging path (k0 eliminated).
// Epilogue: distance (__stcs), log-similarity, logits, per-proto sim sums.
// ---------------------------------------------------------------------------
__global__ __launch_bounds__(256) void k2_dist(
    const float* __restrict__ x, const float* __restrict__ protos,
    const float* __restrict__ llw, float* __restrict__ out) {
    __shared__ uint32_t xs[2][64 * 36];
    __shared__ uint32_t ps[2][48 * 36];
    __shared__ float x2s[64];
    __shared__ float p2s[48];
    __shared__ float wks[96];
    __shared__ float logit_s[128];
    __shared__ float simPart[48];

    const int tid  = threadIdx.x;
    const int lane = tid & 31, warp = tid >> 5;
    const int row0 = blockIdx.x * 64;
    const int g  = lane >> 2;
    const int t4 = lane & 3;

    if (tid < 64)  x2s[tid] = 0.f;
    if (tid < 48)  { p2s[tid] = 0.f; simPart[tid] = 0.f; }
    if (tid < 96)  wks[tid] = llw[tid];
    if (tid < 128) logit_s[tid] = 0.f;

    const int xrow = tid >> 3;            // 0..31 (second x row +32)
    const int xk4  = (tid & 7) << 2;
    const float* xbase  = x + (size_t)(row0 + xrow) * Hd + xk4;
    const float* pbase0 = protos + (size_t)xrow * Hd + xk4;
    const float* pbase1 = protos + (size_t)(xrow + 32) * Hd + xk4;
    const bool   phas1  = (tid < 128);    // proto rows 32..47

    float4 xc0 = __ldcs((const float4*)xbase);
    float4 xc1 = __ldcs((const float4*)(xbase + (size_t)32 * Hd));
    float4 pc0 = __ldg((const float4*)pbase0);
    float4 pc1 = phas1 ? __ldg((const float4*)pbase1) : make_float4(0.f, 0.f, 0.f, 0.f);

    float acc[3][4];
#pragma unroll
    for (int n = 0; n < 3; n++)
#pragma unroll
        for (int q = 0; q < 4; q++) acc[n][q] = 0.f;
    float sq0 = 0.f, sq1 = 0.f, pq0 = 0.f, pq1 = 0.f;

    const int Rg    = (warp & 3) * 16 + g;
    const int nhalf = warp >> 2;

    for (int s = 0; s < 32; s++) {
        const int buf = s & 1;
        // ---- store tile s into buf (accumulating squared norms) ----
        sq0 = fmaf(xc0.x, xc0.x, sq0); sq0 = fmaf(xc0.y, xc0.y, sq0);
        sq0 = fmaf(xc0.z, xc0.z, sq0); sq0 = fmaf(xc0.w, xc0.w, sq0);
        sq1 = fmaf(xc1.x, xc1.x, sq1); sq1 = fmaf(xc1.y, xc1.y, sq1);
        sq1 = fmaf(xc1.z, xc1.z, sq1); sq1 = fmaf(xc1.w, xc1.w, sq1);
        pq0 = fmaf(pc0.x, pc0.x, pq0); pq0 = fmaf(pc0.y, pc0.y, pq0);
        pq0 = fmaf(pc0.z, pc0.z, pq0); pq0 = fmaf(pc0.w, pc0.w, pq0);
        {
            uint4 v;
            v.x = f2tf(xc0.x); v.y = f2tf(xc0.y); v.z = f2tf(xc0.z); v.w = f2tf(xc0.w);
            *(uint4*)&xs[buf][xrow * 36 + xk4] = v;
            v.x = f2tf(xc1.x); v.y = f2tf(xc1.y); v.z = f2tf(xc1.z); v.w = f2tf(xc1.w);
            *(uint4*)&xs[buf][(xrow + 32) * 36 + xk4] = v;
            v.x = f2tf(pc0.x); v.y = f2tf(pc0.y); v.z = f2tf(pc0.z); v.w = f2tf(pc0.w);
            *(uint4*)&ps[buf][xrow * 36 + xk4] = v;
            if (phas1) {
                pq1 = fmaf(pc1.x, pc1.x, pq1); pq1 = fmaf(pc1.y, pc1.y, pq1);
                pq1 = fmaf(pc1.z, pc1.z, pq1); pq1 = fmaf(pc1.w, pc1.w, pq1);
                v.x = f2tf(pc1.x); v.y = f2tf(pc1.y); v.z = f2tf(pc1.z); v.w = f2tf(pc1.w);
                *(uint4*)&ps[buf][(xrow + 32) * 36 + xk4] = v;
            }
        }
        __syncthreads();

        // ---- prefetch tile s+1 (latency hidden under the mma phase) ----
        if (s < 31) {
            const int ko = (s + 1) * 32;
            xc0 = __ldcs((const float4*)(xbase + ko));
            xc1 = __ldcs((const float4*)(xbase + (size_t)32 * Hd + ko));
            pc0 = __ldg((const float4*)(pbase0 + ko));
            if (phas1) pc1 = __ldg((const float4*)(pbase1 + ko));
        }

        // ---- mma over buf ----
#pragma unroll
        for (int kc = 0; kc < 32; kc += 8) {
            const uint32_t a0 = xs[buf][(Rg    ) * 36 + kc + t4];
            const uint32_t a1 = xs[buf][(Rg + 8) * 36 + kc + t4];
            const uint32_t a2 = xs[buf][(Rg    ) * 36 + kc + t4 + 4];
            const uint32_t a3 = xs[buf][(Rg + 8) * 36 + kc + t4 + 4];
#pragma unroll
            for (int nt = 0; nt < 3; nt++) {
                const int prow = (nhalf * 3 + nt) * 8 + g;
                const uint32_t b0 = ps[buf][prow * 36 + kc + t4];
                const uint32_t b1 = ps[buf][prow * 36 + kc + t4 + 4];
                asm volatile(
                    "mma.sync.aligned.m16n8k8.row.col.f32.tf32.tf32.f32 "
                    "{%0,%1,%2,%3}, {%4,%5,%6,%7}, {%8,%9}, {%0,%1,%2,%3};"
                    : "+f"(acc[nt][0]), "+f"(acc[nt][1]),
                      "+f"(acc[nt][2]), "+f"(acc[nt][3])
                    : "r"(a0), "r"(a1), "r"(a2), "r"(a3), "r"(b0), "r"(b1));
            }
        }
    }

    // squared-norm reduction (8 partials per row)
    atomicAdd(&x2s[xrow],      sq0);
    atomicAdd(&x2s[xrow + 32], sq1);
    atomicAdd(&p2s[xrow],      pq0);
    if (phas1) atomicAdd(&p2s[xrow + 32], pq1);
    __syncthreads();

    const int ra = Rg, rb = Rg + 8;
    const float x2a = x2s[ra], x2b = x2s[rb];
    float lgA0 = 0.f, lgA1 = 0.f, lgB0 = 0.f, lgB1 = 0.f;
    float* dd = out + DIST_OFF + (size_t)row0 * 48;
#pragma unroll
    for (int nt = 0; nt < 3; nt++) {
        const int c0 = (nhalf * 3 + nt) * 8 + t4 * 2, c1 = c0 + 1;
        const float dA0 = fmaf(-2.f, acc[nt][0], x2a + p2s[c0]);
        const float dA1 = fmaf(-2.f, acc[nt][1], x2a + p2s[c1]);
        const float dB0 = fmaf(-2.f, acc[nt][2], x2b + p2s[c0]);
        const float dB1 = fmaf(-2.f, acc[nt][3], x2b + p2s[c1]);
        __stcs((float2*)(dd + (size_t)ra * 48 + c0), make_float2(dA0, dA1));
        __stcs((float2*)(dd + (size_t)rb * 48 + c0), make_float2(dB0, dB1));
        const float sA0 = logf((dA0 + 1.f) / (dA0 + EPSf));
        const float sA1 = logf((dA1 + 1.f) / (dA1 + EPSf));
        const float sB0 = logf((dB0 + 1.f) / (dB0 + EPSf));
        const float sB1 = logf((dB1 + 1.f) / (dB1 + EPSf));
        lgA0 = fmaf(sA0, wks[c0], lgA0); lgA0 = fmaf(sA1, wks[c1], lgA0);
        lgA1 = fmaf(sA0, wks[48 + c0], lgA1); lgA1 = fmaf(sA1, wks[48 + c1], lgA1);
        lgB0 = fmaf(sB0, wks[c0], lgB0); lgB0 = fmaf(sB1, wks[c1], lgB0);
        lgB1 = fmaf(sB0, wks[48 + c0], lgB1); lgB1 = fmaf(sB1, wks[48 + c1], lgB1);
        atomicAdd(&simPart[c0], sA0 + sB0);
        atomicAdd(&simPart[c1], sA1 + sB1);
    }
    atomicAdd(&logit_s[ra * 2 + 0], lgA0);
    atomicAdd(&logit_s[ra * 2 + 1], lgA1);
    atomicAdd(&logit_s[rb * 2 + 0], lgB0);
    atomicAdd(&logit_s[rb * 2 + 1], lgB1);
    __syncthreads();

    if (tid < 128) out[LOGITS_OFF + (size_t)row0 * 2 + tid] = logit_s[tid];
    if (tid < 48)  atomicAdd(&g_simSum[tid], simPart[tid]);
}

// ---------------------------------------------------------------------------
// K3: in-block argmax -> u[jstar] to smem -> fused shared copy-out + pos dot.
// 512 threads, 16 rows per block (one warp per row), exact fp32.
// ---------------------------------------------------------------------------
__global__ __launch_bounds__(512) void k3_pos(
    const float* __restrict__ shr, const float* __restrict__ bb,
    const int* __restrict__ flag, float* __restrict__ out) {
    __shared__ float us[Hd];
    __shared__ int   js_s;
    const int tid = threadIdx.x;

    if (tid < 32) {
        const int idx = (flag[0] != 0) ? 1 : 0;
        float v = (tid < PPCc) ? g_simSum[idx * PPCc + tid] : -INFINITY;
        int bj = tid;
        for (int o = 16; o; o >>= 1) {
            const float ov = __shfl_xor_sync(0xffffffffu, v, o);
            const int   oj = __shfl_xor_sync(0xffffffffu, bj, o);
            if (ov > v || (ov == v && oj < bj)) { v = ov; bj = oj; }
        }
        if (tid == 0) js_s = idx * PPCc + bj;
    }
    __syncthreads();
    const int js = js_s;
    for (int i = tid; i < Hd; i += 512) us[i] = g_uall[js * Hd + i];
    __syncthreads();

    const int warp = tid >> 5, lane = tid & 31;
    const int r = blockIdx.x * 16 + warp;
    const float4* src = (const float4*)(shr + (size_t)r * Hd);
    float4*       dst = (float4*)(out + SHARED_OFF + (size_t)r * Hd);
    const float4* uf  = (const float4*)us;
    float acc = 0.f;
#pragma unroll
    for (int t = lane; t < Hd / 4; t += 32) {
        const float4 v = __ldcs(src + t);
        __stcs(dst + t, v);
        const float4 u4 = uf[t];
        acc = fmaf(v.x, u4.x, acc);
        acc = fmaf(v.y, u4.y, acc);
        acc = fmaf(v.z, u4.z, acc);
        acc = fmaf(v.w, u4.w, acc);
    }
    for (int o = 16; o; o >>= 1) acc += __shfl_xor_sync(0xffffffffu, acc, o);
    if (lane == 0) out[POS_OFF + r] = acc + __ldg(bb);
}

// ---------------------------------------------------------------------------
extern "C" void kernel_launch(void* const* d_in, const int* in_sizes, int n_in,
                              void* d_out, int out_size) {
    const float* x      = (const float*)d_in[0];  // specific_user [B,H]
    const float* shr    = (const float*)d_in[1];  // shared_user   [B,H]
    const float* protos = (const float*)d_in[2];  // [P,H]
    const float* llw    = (const float*)d_in[3];  // [C,P]
    const float* W      = (const float*)d_in[4];  // [1,H,H]
    const float* bb     = (const float*)d_in[5];  // [1]
    const int*   flag   = (const int*)d_in[6];    // scalar
    float* out = (float*)d_out;

    // zero scratch via graph-capturable memset nodes (no extra kernel launch)
    void* uall_ptr = nullptr;
    void* ssum_ptr = nullptr;
    cudaGetSymbolAddress(&uall_ptr, g_uall);
    cudaGetSymbolAddress(&ssum_ptr, g_simSum);
    cudaMemsetAsync(uall_ptr, 0, (size_t)Pp * Hd * sizeof(float));
    cudaMemsetAsync(ssum_ptr, 0, (size_t)Pp * sizeof(float));

    k1_uall<<<64, 256>>>(protos, W);
    k2_dist<<<Bsz / 64, 256>>>(x, protos, llw, out);
    k3_pos <<<Bsz / 16, 512>>>(shr, bb, flag, out);
}

// round 6
// speedup vs baseline: 1.6610x; 1.0434x over previous
#include <cuda_runtime.h>
#include <math.h>
#include <stdint.h>

#define Bsz 16384
#define Hd  1024
#define Cc  2
#define PPCc 24
#define Pp  48
#define EPSf 1e-4f

#define UALL_BLOCKS 64
#define DIST_BLOCKS (Bsz / 64)

// Output layout (concatenated reference tuple, all fp32):
//   pos      [B,1]   at 0
//   shared   [B,H]   at B
//   logits   [B,C]   at B + B*H
//   distance [B,P]   at B + B*H + B*C
#define POS_OFF    ((size_t)0)
#define SHARED_OFF ((size_t)Bsz)
#define LOGITS_OFF (SHARED_OFF + (size_t)Bsz * Hd)
#define DIST_OFF   (LOGITS_OFF + (size_t)Bsz * Cc)

// Scratch (no device allocs allowed; zeroed via cudaMemsetAsync graph nodes)
__device__ float g_simSum[Pp];
__device__ float g_uall[Pp * Hd];   // u_p = W^T proto_p, all 48 (exact fp32)

__device__ __forceinline__ uint32_t f2tf(float f) {
    uint32_t r;
    asm("cvt.rna.tf32.f32 %0, %1;" : "=r"(r) : "f"(f));
    return r;
}

// ---------------------------------------------------------------------------
// K2 fused: blocks [0,64) compute u_all (split-K atomics, exact fp32);
// blocks [64,320) run the tf32 distance GEMM. One launch -> the latency-bound
// uall work hides under the dist blocks instead of serializing before them.
// ---------------------------------------------------------------------------
__global__ __launch_bounds__(256) void k2_fused(
    const float* __restrict__ x, const float* __restrict__ protos,
    const float* __restrict__ llw, const float* __restrict__ W,
    float* __restrict__ out) {
    __shared__ uint32_t xs[2][64 * 36];
    __shared__ uint32_t ps[2][48 * 36];
    __shared__ float x2s[64];
    __shared__ float p2s[48];
    __shared__ float wks[96];
    __shared__ float logit_s[128];
    __shared__ float simPart[48];

    const int tid = threadIdx.x;

    // ======================= role: u_all =======================
    if (blockIdx.x < UALL_BLOCKS) {
        float* psh = (float*)&xs[0][0];          // 48*64 floats, fits in xs
        const int b = blockIdx.x;
        const int j0 = (b & 3) * 256;
        const int i0 = (b >> 2) * 64;
        for (int idx = tid; idx < Pp * 64; idx += 256) {
            const int p = idx >> 6, i = idx & 63;
            psh[idx] = protos[(size_t)p * Hd + i0 + i];
        }
        __syncthreads();
        const int j = j0 + tid;
        float acc[Pp];
#pragma unroll
        for (int p = 0; p < Pp; p++) acc[p] = 0.f;
        const float* Wp = W + (size_t)i0 * Hd + j;
        for (int i = 0; i < 64; i += 4) {
            const float w0 = __ldcs(Wp + (size_t)(i + 0) * Hd);
            const float w1 = __ldcs(Wp + (size_t)(i + 1) * Hd);
            const float w2 = __ldcs(Wp + (size_t)(i + 2) * Hd);
            const float w3 = __ldcs(Wp + (size_t)(i + 3) * Hd);
#pragma unroll
            for (int p = 0; p < Pp; p++) {
                const float4 pv = *(const float4*)&psh[p * 64 + i];
                float a = acc[p];
                a = fmaf(w0, pv.x, a); a = fmaf(w1, pv.y, a);
                a = fmaf(w2, pv.z, a); a = fmaf(w3, pv.w, a);
                acc[p] = a;
            }
        }
#pragma unroll
        for (int p = 0; p < Pp; p++)
            atomicAdd(&g_uall[p * Hd + j], acc[p]);
        return;
    }

    // ======================= role: distance GEMM =======================
    const int lane = tid & 31, warp = tid >> 5;
    const int row0 = (blockIdx.x - UALL_BLOCKS) * 64;
    const int g  = lane >> 2;
    const int t4 = lane & 3;

    if (tid < 64)  x2s[tid] = 0.f;
    if (tid < 48)  { p2s[tid] = 0.f; simPart[tid] = 0.f; }
    if (tid < 96)  wks[tid] = llw[tid];
    if (tid < 128) logit_s[tid] = 0.f;

    const int xrow = tid >> 3;            // 0..31 (second x row +32)
    const int xk4  = (tid & 7) << 2;
    const float* xbase  = x + (size_t)(row0 + xrow) * Hd + xk4;
    const float* pbase0 = protos + (size_t)xrow * Hd + xk4;
    const float* pbase1 = protos + (size_t)(xrow + 32) * Hd + xk4;
    const bool   phas1  = (tid < 128);    // proto rows 32..47

    float4 xc0 = __ldcs((const float4*)xbase);
    float4 xc1 = __ldcs((const float4*)(xbase + (size_t)32 * Hd));
    float4 pc0 = __ldg((const float4*)pbase0);
    float4 pc1 = phas1 ? __ldg((const float4*)pbase1) : make_float4(0.f, 0.f, 0.f, 0.f);

    float acc[3][4];
#pragma unroll
    for (int n = 0; n < 3; n++)
#pragma unroll
        for (int q = 0; q < 4; q++) acc[n][q] = 0.f;
    float sq0 = 0.f, sq1 = 0.f, pq0 = 0.f, pq1 = 0.f;

    const int Rg    = (warp & 3) * 16 + g;
    const int nhalf = warp >> 2;

    for (int s = 0; s < 32; s++) {
        const int buf = s & 1;
        // ---- store tile s into buf (accumulating squared norms) ----
        sq0 = fmaf(xc0.x, xc0.x, sq0); sq0 = fmaf(xc0.y, xc0.y, sq0);
        sq0 = fmaf(xc0.z, xc0.z, sq0); sq0 = fmaf(xc0.w, xc0.w, sq0);
        sq1 = fmaf(xc1.x, xc1.x, sq1); sq1 = fmaf(xc1.y, xc1.y, sq1);
        sq1 = fmaf(xc1.z, xc1.z, sq1); sq1 = fmaf(xc1.w, xc1.w, sq1);
        pq0 = fmaf(pc0.x, pc0.x, pq0); pq0 = fmaf(pc0.y, pc0.y, pq0);
        pq0 = fmaf(pc0.z, pc0.z, pq0); pq0 = fmaf(pc0.w, pc0.w, pq0);
        {
            uint4 v;
            v.x = f2tf(xc0.x); v.y = f2tf(xc0.y); v.z = f2tf(xc0.z); v.w = f2tf(xc0.w);
            *(uint4*)&xs[buf][xrow * 36 + xk4] = v;
            v.x = f2tf(xc1.x); v.y = f2tf(xc1.y); v.z = f2tf(xc1.z); v.w = f2tf(xc1.w);
            *(uint4*)&xs[buf][(xrow + 32) * 36 + xk4] = v;
            v.x = f2tf(pc0.x); v.y = f2tf(pc0.y); v.z = f2tf(pc0.z); v.w = f2tf(pc0.w);
            *(uint4*)&ps[buf][xrow * 36 + xk4] = v;
            if (phas1) {
                pq1 = fmaf(pc1.x, pc1.x, pq1); pq1 = fmaf(pc1.y, pc1.y, pq1);
                pq1 = fmaf(pc1.z, pc1.z, pq1); pq1 = fmaf(pc1.w, pc1.w, pq1);
                v.x = f2tf(pc1.x); v.y = f2tf(pc1.y); v.z = f2tf(pc1.z); v.w = f2tf(pc1.w);
                *(uint4*)&ps[buf][(xrow + 32) * 36 + xk4] = v;
            }
        }
        __syncthreads();

        // ---- prefetch tile s+1 (latency hidden under the mma phase) ----
        if (s < 31) {
            const int ko = (s + 1) * 32;
            xc0 = __ldcs((const float4*)(xbase + ko));
            xc1 = __ldcs((const float4*)(xbase + (size_t)32 * Hd + ko));
            pc0 = __ldg((const float4*)(pbase0 + ko));
            if (phas1) pc1 = __ldg((const float4*)(pbase1 + ko));
        }

        // ---- mma over buf ----
#pragma unroll
        for (int kc = 0; kc < 32; kc += 8) {
            const uint32_t a0 = xs[buf][(Rg    ) * 36 + kc + t4];
            const uint32_t a1 = xs[buf][(Rg + 8) * 36 + kc + t4];
            const uint32_t a2 = xs[buf][(Rg    ) * 36 + kc + t4 + 4];
            const uint32_t a3 = xs[buf][(Rg + 8) * 36 + kc + t4 + 4];
#pragma unroll
            for (int nt = 0; nt < 3; nt++) {
                const int prow = (nhalf * 3 + nt) * 8 + g;
                const uint32_t b0 = ps[buf][prow * 36 + kc + t4];
                const uint32_t b1 = ps[buf][prow * 36 + kc + t4 + 4];
                asm volatile(
                    "mma.sync.aligned.m16n8k8.row.col.f32.tf32.tf32.f32 "
                    "{%0,%1,%2,%3}, {%4,%5,%6,%7}, {%8,%9}, {%0,%1,%2,%3};"
                    : "+f"(acc[nt][0]), "+f"(acc[nt][1]),
                      "+f"(acc[nt][2]), "+f"(acc[nt][3])
                    : "r"(a0), "r"(a1), "r"(a2), "r"(a3), "r"(b0), "r"(b1));
            }
        }
    }

    // squared-norm reduction (8 partials per row)
    atomicAdd(&x2s[xrow],      sq0);
    atomicAdd(&x2s[xrow + 32], sq1);
    atomicAdd(&p2s[xrow],      pq0);
    if (phas1) atomicAdd(&p2s[xrow + 32], pq1);
    __syncthreads();

    const int ra = Rg, rb = Rg + 8;
    const float x2a = x2s[ra], x2b = x2s[rb];
    float lgA0 = 0.f, lgA1 = 0.f, lgB0 = 0.f, lgB1 = 0.f;
    float* dd = out + DIST_OFF + (size_t)row0 * 48;
#pragma unroll
    for (int nt = 0; nt < 3; nt++) {
        const int c0 = (nhalf * 3 + nt) * 8 + t4 * 2, c1 = c0 + 1;
        const float dA0 = fmaf(-2.f, acc[nt][0], x2a + p2s[c0]);
        const float dA1 = fmaf(-2.f, acc[nt][1], x2a + p2s[c1]);
        const float dB0 = fmaf(-2.f, acc[nt][2], x2b + p2s[c0]);
        const float dB1 = fmaf(-2.f, acc[nt][3], x2b + p2s[c1]);
        __stcs((float2*)(dd + (size_t)ra * 48 + c0), make_float2(dA0, dA1));
        __stcs((float2*)(dd + (size_t)rb * 48 + c0), make_float2(dB0, dB1));
        const float sA0 = logf((dA0 + 1.f) / (dA0 + EPSf));
        const float sA1 = logf((dA1 + 1.f) / (dA1 + EPSf));
        const float sB0 = logf((dB0 + 1.f) / (dB0 + EPSf));
        const float sB1 = logf((dB1 + 1.f) / (dB1 + EPSf));
        lgA0 = fmaf(sA0, wks[c0], lgA0); lgA0 = fmaf(sA1, wks[c1], lgA0);
        lgA1 = fmaf(sA0, wks[48 + c0], lgA1); lgA1 = fmaf(sA1, wks[48 + c1], lgA1);
        lgB0 = fmaf(sB0, wks[c0], lgB0); lgB0 = fmaf(sB1, wks[c1], lgB0);
        lgB1 = fmaf(sB0, wks[48 + c0], lgB1); lgB1 = fmaf(sB1, wks[48 + c1], lgB1);
        atomicAdd(&simPart[c0], sA0 + sB0);
        atomicAdd(&simPart[c1], sA1 + sB1);
    }
    atomicAdd(&logit_s[ra * 2 + 0], lgA0);
    atomicAdd(&logit_s[ra * 2 + 1], lgA1);
    atomicAdd(&logit_s[rb * 2 + 0], lgB0);
    atomicAdd(&logit_s[rb * 2 + 1], lgB1);
    __syncthreads();

    if (tid < 128) out[LOGITS_OFF + (size_t)row0 * 2 + tid] = logit_s[tid];
    if (tid < 48)  atomicAdd(&g_simSum[tid], simPart[tid]);
}

// ---------------------------------------------------------------------------
// K3: in-block argmax -> u[jstar] to smem -> fused shared copy-out + pos dot.
// 512 threads, 16 rows per block (one warp per row), exact fp32.
// 4 independent accumulators per thread to break the FMA dependence chain.
// ---------------------------------------------------------------------------
__global__ __launch_bounds__(512) void k3_pos(
    const float* __restrict__ shr, const float* __restrict__ bb,
    const int* __restrict__ flag, float* __restrict__ out) {
    __shared__ float us[Hd];
    __shared__ int   js_s;
    const int tid = threadIdx.x;

    if (tid < 32) {
        const int idx = (flag[0] != 0) ? 1 : 0;
        float v = (tid < PPCc) ? g_simSum[idx * PPCc + tid] : -INFINITY;
        int bj = tid;
        for (int o = 16; o; o >>= 1) {
            const float ov = __shfl_xor_sync(0xffffffffu, v, o);
            const int   oj = __shfl_xor_sync(0xffffffffu, bj, o);
            if (ov > v || (ov == v && oj < bj)) { v = ov; bj = oj; }
        }
        if (tid == 0) js_s = idx * PPCc + bj;
    }
    __syncthreads();
    const int js = js_s;
    for (int i = tid; i < Hd; i += 512) us[i] = g_uall[js * Hd + i];
    __syncthreads();

    const int warp = tid >> 5, lane = tid & 31;
    const int r = blockIdx.x * 16 + warp;
    const float4* src = (const float4*)(shr + (size_t)r * Hd);
    float4*       dst = (float4*)(out + SHARED_OFF + (size_t)r * Hd);
    const float4* uf  = (const float4*)us;
    float a0 = 0.f, a1 = 0.f, a2 = 0.f, a3 = 0.f;
#pragma unroll
    for (int t = lane; t < Hd / 4; t += 32) {
        const float4 v = __ldcs(src + t);
        __stcs(dst + t, v);
        const float4 u4 = uf[t];
        a0 = fmaf(v.x, u4.x, a0);
        a1 = fmaf(v.y, u4.y, a1);
        a2 = fmaf(v.z, u4.z, a2);
        a3 = fmaf(v.w, u4.w, a3);
    }
    float acc = (a0 + a1) + (a2 + a3);
    for (int o = 16; o; o >>= 1) acc += __shfl_xor_sync(0xffffffffu, acc, o);
    if (lane == 0) out[POS_OFF + r] = acc + __ldg(bb);
}

// ---------------------------------------------------------------------------
extern "C" void kernel_launch(void* const* d_in, const int* in_sizes, int n_in,
                              void* d_out, int out_size) {
    const float* x      = (const float*)d_in[0];  // specific_user [B,H]
    const float* shr    = (const float*)d_in[1];  // shared_user   [B,H]
    const float* protos = (const float*)d_in[2];  // [P,H]
    const float* llw    = (const float*)d_in[3];  // [C,P]
    const float* W      = (const float*)d_in[4];  // [1,H,H]
    const float* bb     = (const float*)d_in[5];  // [1]
    const int*   flag   = (const int*)d_in[6];    // scalar
    float* out = (float*)d_out;

    // zero scratch via graph-capturable memset nodes (no extra kernel launch)
    void* uall_ptr = nullptr;
    void* ssum_ptr = nullptr;
    cudaGetSymbolAddress(&uall_ptr, g_uall);
    cudaGetSymbolAddress(&ssum_ptr, g_simSum);
    cudaMemsetAsync(uall_ptr, 0, (size_t)Pp * Hd * sizeof(float));
    cudaMemsetAsync(ssum_ptr, 0, (size_t)Pp * sizeof(float));

    k2_fused<<<UALL_BLOCKS + DIST_BLOCKS, 256>>>(x, protos, llw, W, out);
    k3_pos  <<<Bsz / 16, 512>>>(shr, bb, flag, out);
}

// round 7
// speedup vs baseline: 2.2225x; 1.3381x over previous
#include <cuda_runtime.h>
#include <math.h>
#include <stdint.h>

#define Bsz 16384
#define Hd  1024
#define Cc  2
#define PPCc 24
#define Pp  48
#define EPSf 1e-4f

#define UALL_BLOCKS 512
#define DIST_BLOCKS (Bsz / 64)

#define XWORDS (64 * 36)
#define STAGE_WORDS ((64 + 48) * 36)

// Output layout (concatenated reference tuple, all fp32):
//   pos [B,1] | shared [B,H] | logits [B,C] | distance [B,P]
#define POS_OFF    ((size_t)0)
#define SHARED_OFF ((size_t)Bsz)
#define LOGITS_OFF (SHARED_OFF + (size_t)Bsz * Hd)
#define DIST_OFF   (LOGITS_OFF + (size_t)Bsz * Cc)

// Scratch (no device allocs allowed; zeroed via cudaMemsetAsync graph nodes)
__device__ float g_simSum[Pp];
__device__ float g_uall[Pp * Hd];   // u_p = W^T proto_p (exact fp32)

__device__ __forceinline__ void cpa16(uint32_t dst, const void* src) {
    asm volatile("cp.async.cg.shared.global [%0], [%1], 16;"
                 :: "r"(dst), "l"(src));
}
__device__ __forceinline__ void cpa_commit() {
    asm volatile("cp.async.commit_group;" ::: "memory");
}
__device__ __forceinline__ void cpa_wait1() {
    asm volatile("cp.async.wait_group 1;" ::: "memory");
}

// ---------------------------------------------------------------------------
// K2 fused single launch:
//   blocks [0, UALL_BLOCKS):   u_all micro-blocks (exact fp32, split i/j/p)
//   blocks [UALL_BLOCKS, ..):  tf32 distance GEMM, cp.async 3-deep pipeline
// ---------------------------------------------------------------------------
__global__ __launch_bounds__(256, 3) void k2_fused(
    const float* __restrict__ x, const float* __restrict__ protos,
    const float* __restrict__ llw, const float* __restrict__ W,
    float* __restrict__ out) {
    __shared__ uint32_t pipe[3][STAGE_WORDS];   // 48384 B

    const int tid = threadIdx.x;

    // ======================= role: u_all =======================
    if (blockIdx.x < UALL_BLOCKS) {
        float* psh = (float*)&pipe[0][0];      // 24*16 floats
        const int b  = blockIdx.x;
        const int j0 = (b & 3) * 256;
        const int i0 = ((b >> 2) & 63) * 16;
        const int ph = b >> 8;                 // proto half: 0 or 1
        if (tid < 24 * 16) {
            const int p = tid >> 4, i = tid & 15;
            psh[tid] = protos[(size_t)(ph * 24 + p) * Hd + i0 + i];
        }
        __syncthreads();
        const int j = j0 + tid;
        float acc[24];
#pragma unroll
        for (int p = 0; p < 24; p++) acc[p] = 0.f;
        const float* Wp = W + (size_t)i0 * Hd + j;
#pragma unroll
        for (int i = 0; i < 16; i += 8) {
            float w[8];
#pragma unroll
            for (int q = 0; q < 8; q++) w[q] = __ldcs(Wp + (size_t)(i + q) * Hd);
#pragma unroll
            for (int p = 0; p < 24; p++) {
                float a = acc[p];
#pragma unroll
                for (int q = 0; q < 8; q++) a = fmaf(w[q], psh[p * 16 + i + q], a);
                acc[p] = a;
            }
        }
#pragma unroll
        for (int p = 0; p < 24; p++)
            atomicAdd(&g_uall[(ph * 24 + p) * Hd + j], acc[p]);
        return;
    }

    // ======================= role: distance GEMM =======================
    const int lane = tid & 31, warp = tid >> 5;
    const int row0 = (blockIdx.x - UALL_BLOCKS) * 64;
    const int g  = lane >> 2;
    const int t4 = lane & 3;

    const int xrow = tid >> 3;                 // 0..31
    const int xk4  = (tid & 7) << 2;
    const float* xbase  = x + (size_t)(row0 + xrow) * Hd + xk4;
    const float* pbase0 = protos + (size_t)xrow * Hd + xk4;
    const float* pbase1 = protos + (size_t)(xrow + 32) * Hd + xk4;
    const bool   phas1  = (tid < 128);         // proto rows 32..47

    const uint32_t smem0 = (uint32_t)__cvta_generic_to_shared(&pipe[0][0]);
    const uint32_t dx0 = (xrow * 36 + xk4) * 4;
    const uint32_t dx1 = ((xrow + 32) * 36 + xk4) * 4;
    const uint32_t dp0 = (XWORDS + xrow * 36 + xk4) * 4;
    const uint32_t dp1 = (XWORDS + (xrow + 32) * 36 + xk4) * 4;

#define ISSUE_STAGE(S, BUF)                                              \
    do {                                                                 \
        const int _ko = (S) * 32;                                        \
        const uint32_t _b = smem0 + (BUF) * (STAGE_WORDS * 4);           \
        cpa16(_b + dx0, xbase + _ko);                                    \
        cpa16(_b + dx1, xbase + (size_t)32 * Hd + _ko);                  \
        cpa16(_b + dp0, pbase0 + _ko);                                   \
        if (phas1) cpa16(_b + dp1, pbase1 + _ko);                        \
    } while (0)

    ISSUE_STAGE(0, 0); cpa_commit();
    ISSUE_STAGE(1, 1); cpa_commit();

    float acc[3][4];
#pragma unroll
    for (int n = 0; n < 3; n++)
#pragma unroll
        for (int q = 0; q < 4; q++) acc[n][q] = 0.f;
    float sqA = 0.f, sqB = 0.f;
    float pq[3] = {0.f, 0.f, 0.f};

    const int Rg    = (warp & 3) * 16 + g;
    const int nhalf = warp >> 2;
    const bool doX2 = (nhalf == 0);
    const bool doP2 = ((warp & 3) == 0);

    for (int s = 0; s < 32; s++) {
        cpa_wait1();
        __syncthreads();
        if (s + 2 < 32) { const int b2 = (s + 2) % 3; ISSUE_STAGE(s + 2, b2); }
        cpa_commit();

        const uint32_t* xb = &pipe[s % 3][0];
        const uint32_t* pb = xb + XWORDS;
#pragma unroll
        for (int kc = 0; kc < 32; kc += 8) {
            const uint32_t a0 = xb[(Rg    ) * 36 + kc + t4];
            const uint32_t a1 = xb[(Rg + 8) * 36 + kc + t4];
            const uint32_t a2 = xb[(Rg    ) * 36 + kc + t4 + 4];
            const uint32_t a3 = xb[(Rg + 8) * 36 + kc + t4 + 4];
            if (doX2) {
                const float f0 = __uint_as_float(a0), f1 = __uint_as_float(a1);
                const float f2 = __uint_as_float(a2), f3 = __uint_as_float(a3);
                sqA = fmaf(f0, f0, sqA); sqA = fmaf(f2, f2, sqA);
                sqB = fmaf(f1, f1, sqB); sqB = fmaf(f3, f3, sqB);
            }
#pragma unroll
            for (int nt = 0; nt < 3; nt++) {
                const int prow = (nhalf * 3 + nt) * 8 + g;
                const uint32_t b0 = pb[prow * 36 + kc + t4];
                const uint32_t b1 = pb[prow * 36 + kc + t4 + 4];
                if (doP2) {
                    const float h0 = __uint_as_float(b0), h1 = __uint_as_float(b1);
                    pq[nt] = fmaf(h0, h0, pq[nt]);
                    pq[nt] = fmaf(h1, h1, pq[nt]);
                }
                asm volatile(
                    "mma.sync.aligned.m16n8k8.row.col.f32.tf32.tf32.f32 "
                    "{%0,%1,%2,%3}, {%4,%5,%6,%7}, {%8,%9}, {%0,%1,%2,%3};"
                    : "+f"(acc[nt][0]), "+f"(acc[nt][1]),
                      "+f"(acc[nt][2]), "+f"(acc[nt][3])
                    : "r"(a0), "r"(a1), "r"(a2), "r"(a3), "r"(b0), "r"(b1));
            }
        }
    }
    __syncthreads();   // all mma done; safe to alias pipe as epilogue scratch

    // aliased epilogue scratch in pipe[0]
    float* ext     = (float*)&pipe[0][0];
    float* x2s     = ext;          // 64
    float* p2s     = ext + 64;     // 48
    float* logit_s = ext + 112;    // 128
    float* simPart = ext + 240;    // 48
    float* wks     = ext + 288;    // 96
    for (int i = tid; i < 384; i += 256)
        ext[i] = (i < 288) ? 0.f : llw[i - 288];
    __syncthreads();

    // quad-reduce squared norms (lanes t4=0..3 share a row)
    sqA += __shfl_xor_sync(0xffffffffu, sqA, 1);
    sqA += __shfl_xor_sync(0xffffffffu, sqA, 2);
    sqB += __shfl_xor_sync(0xffffffffu, sqB, 1);
    sqB += __shfl_xor_sync(0xffffffffu, sqB, 2);
    if (doX2 && t4 == 0) {
        atomicAdd(&x2s[Rg],     sqA);
        atomicAdd(&x2s[Rg + 8], sqB);
    }
#pragma unroll
    for (int nt = 0; nt < 3; nt++) {
        pq[nt] += __shfl_xor_sync(0xffffffffu, pq[nt], 1);
        pq[nt] += __shfl_xor_sync(0xffffffffu, pq[nt], 2);
    }
    if (doP2 && t4 == 0) {
#pragma unroll
        for (int nt = 0; nt < 3; nt++)
            atomicAdd(&p2s[(nhalf * 3 + nt) * 8 + g], pq[nt]);
    }
    __syncthreads();

    const int ra = Rg, rb = Rg + 8;
    const float x2a = x2s[ra], x2b = x2s[rb];
    float lgA0 = 0.f, lgA1 = 0.f, lgB0 = 0.f, lgB1 = 0.f;
    float* dd = out + DIST_OFF + (size_t)row0 * 48;
#pragma unroll
    for (int nt = 0; nt < 3; nt++) {
        const int c0 = (nhalf * 3 + nt) * 8 + t4 * 2, c1 = c0 + 1;
        const float dA0 = fmaf(-2.f, acc[nt][0], x2a + p2s[c0]);
        const float dA1 = fmaf(-2.f, acc[nt][1], x2a + p2s[c1]);
        const float dB0 = fmaf(-2.f, acc[nt][2], x2b + p2s[c0]);
        const float dB1 = fmaf(-2.f, acc[nt][3], x2b + p2s[c1]);
        __stcs((float2*)(dd + (size_t)ra * 48 + c0), make_float2(dA0, dA1));
        __stcs((float2*)(dd + (size_t)rb * 48 + c0), make_float2(dB0, dB1));
        const float sA0 = logf((dA0 + 1.f) / (dA0 + EPSf));
        const float sA1 = logf((dA1 + 1.f) / (dA1 + EPSf));
        const float sB0 = logf((dB0 + 1.f) / (dB0 + EPSf));
        const float sB1 = logf((dB1 + 1.f) / (dB1 + EPSf));
        lgA0 = fmaf(sA0, wks[c0], lgA0); lgA0 = fmaf(sA1, wks[c1], lgA0);
        lgA1 = fmaf(sA0, wks[48 + c0], lgA1); lgA1 = fmaf(sA1, wks[48 + c1], lgA1);
        lgB0 = fmaf(sB0, wks[c0], lgB0); lgB0 = fmaf(sB1, wks[c1], lgB0);
        lgB1 = fmaf(sB0, wks[48 + c0], lgB1); lgB1 = fmaf(sB1, wks[48 + c1], lgB1);
        atomicAdd(&simPart[c0], sA0 + sB0);
        atomicAdd(&simPart[c1], sA1 + sB1);
    }
    atomicAdd(&logit_s[ra * 2 + 0], lgA0);
    atomicAdd(&logit_s[ra * 2 + 1], lgA1);
    atomicAdd(&logit_s[rb * 2 + 0], lgB0);
    atomicAdd(&logit_s[rb * 2 + 1], lgB1);
    __syncthreads();

    if (tid < 128) out[LOGITS_OFF + (size_t)row0 * 2 + tid] = logit_s[tid];
    if (tid < 48)  atomicAdd(&g_simSum[tid], simPart[tid]);
#undef ISSUE_STAGE
}

// ---------------------------------------------------------------------------
// K3: in-block argmax -> u[jstar] to smem -> fused shared copy-out + pos dot.
// ---------------------------------------------------------------------------
__global__ __launch_bounds__(512) void k3_pos(
    const float* __restrict__ shr, const float* __restrict__ bb,
    const int* __restrict__ flag, float* __restrict__ out) {
    __shared__ float us[Hd];
    __shared__ int   js_s;
    const int tid = threadIdx.x;

    if (tid < 32) {
        const int idx = (flag[0] != 0) ? 1 : 0;
        float v = (tid < PPCc) ? g_simSum[idx * PPCc + tid] : -INFINITY;
        int bj = tid;
        for (int o = 16; o; o >>= 1) {
            const float ov = __shfl_xor_sync(0xffffffffu, v, o);
            const int   oj = __shfl_xor_sync(0xffffffffu, bj, o);
            if (ov > v || (ov == v && oj < bj)) { v = ov; bj = oj; }
        }
        if (tid == 0) js_s = idx * PPCc + bj;
    }
    __syncthreads();
    const int js = js_s;
    for (int i = tid; i < Hd; i += 512) us[i] = g_uall[js * Hd + i];
    __syncthreads();

    const int warp = tid >> 5, lane = tid & 31;
    const int r = blockIdx.x * 16 + warp;
    const float4* src = (const float4*)(shr + (size_t)r * Hd);
    float4*       dst = (float4*)(out + SHARED_OFF + (size_t)r * Hd);
    const float4* uf  = (const float4*)us;
    float a0 = 0.f, a1 = 0.f, a2 = 0.f, a3 = 0.f;
#pragma unroll
    for (int t = lane; t < Hd / 4; t += 32) {
        const float4 v = __ldcs(src + t);
        __stcs(dst + t, v);
        const float4 u4 = uf[t];
        a0 = fmaf(v.x, u4.x, a0);
        a1 = fmaf(v.y, u4.y, a1);
        a2 = fmaf(v.z, u4.z, a2);
        a3 = fmaf(v.w, u4.w, a3);
    }
    float acc = (a0 + a1) + (a2 + a3);
    for (int o = 16; o; o >>= 1) acc += __shfl_xor_sync(0xffffffffu, acc, o);
    if (lane == 0) out[POS_OFF + r] = acc + __ldg(bb);
}

// ---------------------------------------------------------------------------
extern "C" void kernel_launch(void* const* d_in, const int* in_sizes, int n_in,
                              void* d_out, int out_size) {
    const float* x      = (const float*)d_in[0];  // specific_user [B,H]
    const float* shr    = (const float*)d_in[1];  // shared_user   [B,H]
    const float* protos = (const float*)d_in[2];  // [P,H]
    const float* llw    = (const float*)d_in[3];  // [C,P]
    const float* W      = (const float*)d_in[4];  // [1,H,H]
    const float* bb     = (const float*)d_in[5];  // [1]
    const int*   flag   = (const int*)d_in[6];    // scalar
    float* out = (float*)d_out;

    void* uall_ptr = nullptr;
    void* ssum_ptr = nullptr;
    cudaGetSymbolAddress(&uall_ptr, g_uall);
    cudaGetSymbolAddress(&ssum_ptr, g_simSum);
    cudaMemsetAsync(uall_ptr, 0, (size_t)Pp * Hd * sizeof(float));
    cudaMemsetAsync(ssum_ptr, 0, (size_t)Pp * sizeof(float));

    k2_fused<<<UALL_BLOCKS + DIST_BLOCKS, 256>>>(x, protos, llw, W, out);
    k3_pos  <<<Bsz / 16, 512>>>(shr, bb, flag, out);
}